// round 8
// baseline (speedup 1.0000x reference)
#include <cuda_runtime.h>
#include <math.h>

#define BB 8
#define CC 512
#define LL 2048

// Scratch (static device globals — no allocation)
__device__ float g_q[BB * CC * LL];
__device__ float g_k[BB * CC * LL];
__device__ float g_v[BB * CC * LL];
__device__ float g_s[(size_t)BB * LL * LL];

// ---------------------------------------------------------------------------
// tf32 mma.sync GEMM: C[m,n] = scale * sum_k A(m,k)*B(k,n) + bias[m]
//   TA=false: A row-major MxK (A[m*lda+k]);  TA=true: A is KxM (A[k*lda+m])
//   TB=false: B row-major KxN (B[k*ldb+n]);  TB=true: B is NxK (B[n*ldb+k])
// Block: 128x128, 256 threads (8 warps, 2 in M x 4 in N), warp tile 64x32.
// BK=16 -> 2 k-steps of m16n8k8 per tile. All dims multiples of 128/16.
// ---------------------------------------------------------------------------
constexpr int BM = 128, BN = 128, BK = 16;
constexpr int SA = 136;   // padded row stride (136 mod 32 == 8 -> conflict-free frags)

__device__ __forceinline__ unsigned f2tf(float f) {
    unsigned u;
    asm("cvt.rna.tf32.f32 %0, %1;" : "=r"(u) : "f"(f));
    return u;
}

__device__ __forceinline__ void mma_tf32(float* d, const unsigned* a, const unsigned* b) {
    asm volatile(
        "mma.sync.aligned.m16n8k8.row.col.f32.tf32.tf32.f32 "
        "{%0,%1,%2,%3}, {%4,%5,%6,%7}, {%8,%9}, {%0,%1,%2,%3};"
        : "+f"(d[0]), "+f"(d[1]), "+f"(d[2]), "+f"(d[3])
        : "r"(a[0]), "r"(a[1]), "r"(a[2]), "r"(a[3]), "r"(b[0]), "r"(b[1]));
}

template <bool TA, bool TB>
__device__ __forceinline__ void gemm_body(
    const float* __restrict__ A, const float* __restrict__ B,
    float* __restrict__ C, int K,
    int lda, int ldb, int ldc,
    float scale, const float* __restrict__ bias)
{
    __shared__ unsigned As[BK][SA];
    __shared__ unsigned Bs[BK][SA];

    const int tid  = threadIdx.x;
    const int lane = tid & 31;
    const int warp = tid >> 5;
    const int wm = warp & 1;        // 0..1  (M dir, 64 rows each)
    const int wn = warp >> 1;       // 0..3  (N dir, 32 cols each)
    const int r = lane >> 2;        // groupID           0..7
    const int c = lane & 3;         // threadID_in_group 0..3
    const int m0 = blockIdx.y * BM;
    const int n0 = blockIdx.x * BN;

    float acc[4][4][4];
#pragma unroll
    for (int i = 0; i < 4; i++)
#pragma unroll
        for (int j = 0; j < 4; j++)
#pragma unroll
            for (int q = 0; q < 4; q++) acc[i][j][q] = 0.0f;

    float4 pa[2], pb[2];

    // ---- global loads into regs (2 float4 each for A and B tile) ----
    auto ldA = [&](int k0) {
#pragma unroll
        for (int it = 0; it < 2; it++) {
            const int chunk = tid + 256 * it;
            if (!TA) {
                const int m = chunk & 127, k4 = chunk >> 7;          // k4: 0..3
                pa[it] = *(const float4*)&A[(size_t)(m0 + m) * lda + k0 + 4 * k4];
            } else {
                const int kk = chunk >> 5, m4 = chunk & 31;          // kk: 0..15
                pa[it] = *(const float4*)&A[(size_t)(k0 + kk) * lda + m0 + 4 * m4];
            }
        }
    };
    auto ldB = [&](int k0) {
#pragma unroll
        for (int it = 0; it < 2; it++) {
            const int chunk = tid + 256 * it;
            if (!TB) {
                const int kk = chunk >> 5, n4 = chunk & 31;
                pb[it] = *(const float4*)&B[(size_t)(k0 + kk) * ldb + n0 + 4 * n4];
            } else {
                const int n = chunk & 127, k4 = chunk >> 7;
                pb[it] = *(const float4*)&B[(size_t)(n0 + n) * ldb + k0 + 4 * k4];
            }
        }
    };
    auto stA = [&]() {
#pragma unroll
        for (int it = 0; it < 2; it++) {
            const int chunk = tid + 256 * it;
            if (!TA) {
                const int m = chunk & 127, k4 = chunk >> 7;
                As[4 * k4 + 0][m] = f2tf(pa[it].x);
                As[4 * k4 + 1][m] = f2tf(pa[it].y);
                As[4 * k4 + 2][m] = f2tf(pa[it].z);
                As[4 * k4 + 3][m] = f2tf(pa[it].w);
            } else {
                const int kk = chunk >> 5, m4 = chunk & 31;
                uint4 v = make_uint4(f2tf(pa[it].x), f2tf(pa[it].y),
                                     f2tf(pa[it].z), f2tf(pa[it].w));
                *(uint4*)&As[kk][4 * m4] = v;
            }
        }
    };
    auto stB = [&]() {
#pragma unroll
        for (int it = 0; it < 2; it++) {
            const int chunk = tid + 256 * it;
            if (!TB) {
                const int kk = chunk >> 5, n4 = chunk & 31;
                uint4 v = make_uint4(f2tf(pb[it].x), f2tf(pb[it].y),
                                     f2tf(pb[it].z), f2tf(pb[it].w));
                *(uint4*)&Bs[kk][4 * n4] = v;
            } else {
                const int n = chunk & 127, k4 = chunk >> 7;
                Bs[4 * k4 + 0][n] = f2tf(pb[it].x);
                Bs[4 * k4 + 1][n] = f2tf(pb[it].y);
                Bs[4 * k4 + 2][n] = f2tf(pb[it].z);
                Bs[4 * k4 + 3][n] = f2tf(pb[it].w);
            }
        }
    };
    auto compute = [&]() {
#pragma unroll
        for (int ks = 0; ks < 2; ks++) {
            const int kb = ks * 8;
            unsigned af[4][4], bf[4][2];
#pragma unroll
            for (int i = 0; i < 4; i++) {
                const int mb = wm * 64 + i * 16;
                af[i][0] = As[kb + c][mb + r];
                af[i][1] = As[kb + c][mb + r + 8];
                af[i][2] = As[kb + c + 4][mb + r];
                af[i][3] = As[kb + c + 4][mb + r + 8];
            }
#pragma unroll
            for (int j = 0; j < 4; j++) {
                const int nb = wn * 32 + j * 8;
                bf[j][0] = Bs[kb + c][nb + r];
                bf[j][1] = Bs[kb + c + 4][nb + r];
            }
#pragma unroll
            for (int i = 0; i < 4; i++)
#pragma unroll
                for (int j = 0; j < 4; j++)
                    mma_tf32(acc[i][j], af[i], bf[j]);
        }
    };

    // ---- pipelined mainloop ----
    ldA(0); ldB(0);
    stA(); stB();
    __syncthreads();
    for (int k0 = BK;; k0 += BK) {
        const bool more = (k0 < K);
        if (more) { ldA(k0); ldB(k0); }
        compute();
        if (!more) break;
        __syncthreads();
        stA(); stB();
        __syncthreads();
    }

    // ---- epilogue ----
#pragma unroll
    for (int i = 0; i < 4; i++) {
        const int m = m0 + wm * 64 + i * 16 + r;
        const float bv0 = bias ? __ldg(&bias[m])     : 0.0f;
        const float bv1 = bias ? __ldg(&bias[m + 8]) : 0.0f;
#pragma unroll
        for (int j = 0; j < 4; j++) {
            const int n = n0 + wn * 32 + j * 8 + 2 * c;
            float2 v0 = make_float2(acc[i][j][0] * scale + bv0,
                                    acc[i][j][1] * scale + bv0);
            *(float2*)&C[(size_t)m * ldc + n] = v0;
            float2 v1 = make_float2(acc[i][j][2] * scale + bv1,
                                    acc[i][j][3] * scale + bv1);
            *(float2*)&C[(size_t)(m + 8) * ldc + n] = v1;
        }
    }
}

// ---------------------------------------------------------------------------
// Kernel 1: QKV projection. grid = (LL/128, CC/128, 3*BB)
// ---------------------------------------------------------------------------
__global__ __launch_bounds__(256) void qkv_kernel(
    const float* __restrict__ x,
    const float* __restrict__ Wq, const float* __restrict__ bq,
    const float* __restrict__ Wk, const float* __restrict__ bk,
    const float* __restrict__ Wv, const float* __restrict__ bv)
{
    const int z = blockIdx.z;
    const int p = z >> 3;
    const int b = z & 7;
    const float* W  = (p == 0) ? Wq : (p == 1) ? Wk : Wv;
    const float* bi = (p == 0) ? bq : (p == 1) ? bk : bv;
    float* out = ((p == 0) ? g_q : (p == 1) ? g_k : g_v) + (size_t)b * CC * LL;
    const float* xb = x + (size_t)b * CC * LL;
    gemm_body<false, false>(W, xb, out, CC, CC, LL, LL, 1.0f, bi);
}

// ---------------------------------------------------------------------------
// Kernel 2: scores = Q^T K / sqrt(C). grid = (LL/128, LL/128, BB)
// ---------------------------------------------------------------------------
__global__ __launch_bounds__(256) void scores_kernel()
{
    const int b = blockIdx.z;
    const float* Q  = g_q + (size_t)b * CC * LL;
    const float* Kp = g_k + (size_t)b * CC * LL;
    float* S = g_s + (size_t)b * LL * LL;
    gemm_body<true, false>(Q, Kp, S, CC, LL, LL, LL,
                           0.044194173824159216f, nullptr);
}

// ---------------------------------------------------------------------------
// Kernel 3: row softmax over m. One block per row. grid = BB*LL
// ---------------------------------------------------------------------------
__global__ __launch_bounds__(256) void softmax_kernel()
{
    const int tid = threadIdx.x;
    float* row = g_s + (size_t)blockIdx.x * LL;

    float v[8];
    float mx = -3.402823466e38f;
#pragma unroll
    for (int i = 0; i < 8; i++) {
        v[i] = row[tid + (i << 8)];
        mx = fmaxf(mx, v[i]);
    }
    __shared__ float red[256];
    red[tid] = mx;
    __syncthreads();
    for (int s = 128; s >= 1; s >>= 1) {
        if (tid < s) red[tid] = fmaxf(red[tid], red[tid + s]);
        __syncthreads();
    }
    mx = red[0];
    __syncthreads();

    float sum = 0.0f;
#pragma unroll
    for (int i = 0; i < 8; i++) {
        v[i] = __expf(v[i] - mx);
        sum += v[i];
    }
    red[tid] = sum;
    __syncthreads();
    for (int s = 128; s >= 1; s >>= 1) {
        if (tid < s) red[tid] += red[tid + s];
        __syncthreads();
    }
    const float inv = __frcp_rn(red[0]);
#pragma unroll
    for (int i = 0; i < 8; i++)
        row[tid + (i << 8)] = v[i] * inv;
}

// ---------------------------------------------------------------------------
// Kernel 4: out = V @ attn^T. grid = (LL/128, CC/128, BB)
// ---------------------------------------------------------------------------
__global__ __launch_bounds__(256) void out_kernel(float* __restrict__ out)
{
    const int b = blockIdx.z;
    const float* V = g_v + (size_t)b * CC * LL;
    const float* P = g_s + (size_t)b * LL * LL;
    float* O = out + (size_t)b * CC * LL;
    gemm_body<false, true>(V, P, O, LL, LL, LL, LL, 1.0f, nullptr);
}

// ---------------------------------------------------------------------------
extern "C" void kernel_launch(void* const* d_in, const int* in_sizes, int n_in,
                              void* d_out, int out_size)
{
    const float* x  = (const float*)d_in[0];
    const float* Wq = (const float*)d_in[1];
    const float* bq = (const float*)d_in[2];
    const float* Wk = (const float*)d_in[3];
    const float* bk = (const float*)d_in[4];
    const float* Wv = (const float*)d_in[5];
    const float* bv = (const float*)d_in[6];
    float* out = (float*)d_out;

    dim3 blk(256);

    dim3 g1(LL / BN, CC / BM, 3 * BB);
    qkv_kernel<<<g1, blk>>>(x, Wq, bq, Wk, bk, Wv, bv);

    dim3 g2(LL / BN, LL / BM, BB);
    scores_kernel<<<g2, blk>>>();

    softmax_kernel<<<BB * LL, blk>>>();

    dim3 g4(LL / BN, CC / BM, BB);
    out_kernel<<<g4, blk>>>(out);
}

// round 10
// speedup vs baseline: 1.0108x; 1.0108x over previous
#include <cuda_runtime.h>
#include <cstdint>
#include <math.h>

#define BB 8
#define CC 512
#define LL 2048

// ---------------- global scratch (no allocation) ----------------
__device__ float g_wr[3 * CC * CC];            // tf32-rounded W (q,k,v concat)
__device__ float g_xr[BB * CC * LL];           // tf32-rounded x
__device__ float g_q[BB * CC * LL];            // tf32-rounded q  [b][c][l]
__device__ float g_k[BB * CC * LL];            // tf32-rounded k  [b][c][l]
__device__ float g_v[BB * CC * LL];            // tf32-rounded v  [b][c][l]
__device__ float g_s[(size_t)BB * LL * LL];    // scores, then tf32-rounded P

__device__ __forceinline__ float tf32r(float f) {
    unsigned u;
    asm("cvt.rna.tf32.f32 %0, %1;" : "=r"(u) : "f"(f));
    return __uint_as_float(u);
}

__device__ __forceinline__ void mma_tf32(float* d, const float* a, const float* b) {
    asm volatile(
        "mma.sync.aligned.m16n8k8.row.col.f32.tf32.tf32.f32 "
        "{%0,%1,%2,%3}, {%4,%5,%6,%7}, {%8,%9}, {%0,%1,%2,%3};"
        : "+f"(d[0]), "+f"(d[1]), "+f"(d[2]), "+f"(d[3])
        : "r"(__float_as_uint(a[0])), "r"(__float_as_uint(a[1])),
          "r"(__float_as_uint(a[2])), "r"(__float_as_uint(a[3])),
          "r"(__float_as_uint(b[0])), "r"(__float_as_uint(b[1])));
}

// ---------------------------------------------------------------------------
// tf32 mma.sync GEMM, double-buffered, one sync per k-tile.
// C[m,n] = scale * sum_k A(m,k)*B(k,n) + bias[m]
//   TA=false: A row-major MxK;  TA=true: A is KxM
//   TB=false: B row-major KxN;  TB=true: B is NxK
// ROUND: round outputs to tf32 before store.
// Block 128x128, 256 threads, 8 warps (2M x 4N), warp tile 64x32, BK=16.
// Operands in gmem are ALREADY tf32-rounded -> no cvt in the hot loop.
// ---------------------------------------------------------------------------
constexpr int BM = 128, BN = 128, BK = 16;
constexpr int SA = 136;   // 136 mod 32 == 8 -> conflict-free fragment LDS

template <bool TA, bool TB, bool ROUND>
__device__ __forceinline__ void gemm_body(
    const float* __restrict__ A, const float* __restrict__ B,
    float* __restrict__ C, int K,
    int lda, int ldb, int ldc,
    float scale, const float* __restrict__ bias)
{
    __shared__ float As[2][BK][SA];
    __shared__ float Bs[2][BK][SA];

    const int tid  = threadIdx.x;
    const int lane = tid & 31;
    const int warp = tid >> 5;
    const int wm = warp & 1;
    const int wn = warp >> 1;
    const int r = lane >> 2;
    const int c = lane & 3;
    const int m0 = blockIdx.y * BM;
    const int n0 = blockIdx.x * BN;

    float acc[4][4][4];
#pragma unroll
    for (int i = 0; i < 4; i++)
#pragma unroll
        for (int j = 0; j < 4; j++)
#pragma unroll
            for (int q = 0; q < 4; q++) acc[i][j][q] = 0.0f;

    float4 pa[2], pb[2];

    auto ldA = [&](int k0) {
#pragma unroll
        for (int it = 0; it < 2; it++) {
            const int chunk = tid + 256 * it;
            if (!TA) {
                const int m = chunk & 127, k4 = chunk >> 7;
                pa[it] = *(const float4*)&A[(size_t)(m0 + m) * lda + k0 + 4 * k4];
            } else {
                const int kk = chunk >> 5, m4 = chunk & 31;
                pa[it] = *(const float4*)&A[(size_t)(k0 + kk) * lda + m0 + 4 * m4];
            }
        }
    };
    auto ldB = [&](int k0) {
#pragma unroll
        for (int it = 0; it < 2; it++) {
            const int chunk = tid + 256 * it;
            if (!TB) {
                const int kk = chunk >> 5, n4 = chunk & 31;
                pb[it] = *(const float4*)&B[(size_t)(k0 + kk) * ldb + n0 + 4 * n4];
            } else {
                const int n = chunk & 127, k4 = chunk >> 7;
                pb[it] = *(const float4*)&B[(size_t)(n0 + n) * ldb + k0 + 4 * k4];
            }
        }
    };
    auto stA = [&](int buf) {
#pragma unroll
        for (int it = 0; it < 2; it++) {
            const int chunk = tid + 256 * it;
            if (!TA) {
                const int m = chunk & 127, k4 = chunk >> 7;
                As[buf][4 * k4 + 0][m] = pa[it].x;
                As[buf][4 * k4 + 1][m] = pa[it].y;
                As[buf][4 * k4 + 2][m] = pa[it].z;
                As[buf][4 * k4 + 3][m] = pa[it].w;
            } else {
                const int kk = chunk >> 5, m4 = chunk & 31;
                *(float4*)&As[buf][kk][4 * m4] = pa[it];
            }
        }
    };
    auto stB = [&](int buf) {
#pragma unroll
        for (int it = 0; it < 2; it++) {
            const int chunk = tid + 256 * it;
            if (!TB) {
                const int kk = chunk >> 5, n4 = chunk & 31;
                *(float4*)&Bs[buf][kk][4 * n4] = pb[it];
            } else {
                const int n = chunk & 127, k4 = chunk >> 7;
                Bs[buf][4 * k4 + 0][n] = pb[it].x;
                Bs[buf][4 * k4 + 1][n] = pb[it].y;
                Bs[buf][4 * k4 + 2][n] = pb[it].z;
                Bs[buf][4 * k4 + 3][n] = pb[it].w;
            }
        }
    };
    auto compute = [&](int buf) {
#pragma unroll
        for (int ks = 0; ks < 2; ks++) {
            const int kb = ks * 8;
            float af[4][4], bf[4][2];
#pragma unroll
            for (int i = 0; i < 4; i++) {
                const int mb = wm * 64 + i * 16;
                af[i][0] = As[buf][kb + c][mb + r];
                af[i][1] = As[buf][kb + c][mb + r + 8];
                af[i][2] = As[buf][kb + c + 4][mb + r];
                af[i][3] = As[buf][kb + c + 4][mb + r + 8];
            }
#pragma unroll
            for (int j = 0; j < 4; j++) {
                const int nb = wn * 32 + j * 8;
                bf[j][0] = Bs[buf][kb + c][nb + r];
                bf[j][1] = Bs[buf][kb + c + 4][nb + r];
            }
#pragma unroll
            for (int i = 0; i < 4; i++)
#pragma unroll
                for (int j = 0; j < 4; j++)
                    mma_tf32(acc[i][j], af[i], bf[j]);
        }
    };

    // prologue: fill buffer 0
    ldA(0); ldB(0);
    stA(0); stB(0);
    __syncthreads();

    // mainloop: ONE sync per tile; st goes to the other buffer during compute
    for (int k0 = 0; k0 < K; k0 += BK) {
        const int cur = (k0 / BK) & 1;
        const bool more = (k0 + BK) < K;
        if (more) { ldA(k0 + BK); ldB(k0 + BK); }
        compute(cur);
        if (more) {
            stA(cur ^ 1); stB(cur ^ 1);
            __syncthreads();
        }
    }

    // epilogue
#pragma unroll
    for (int i = 0; i < 4; i++) {
        const int m = m0 + wm * 64 + i * 16 + r;
        const float bv0 = bias ? __ldg(&bias[m])     : 0.0f;
        const float bv1 = bias ? __ldg(&bias[m + 8]) : 0.0f;
#pragma unroll
        for (int j = 0; j < 4; j++) {
            const int n = n0 + wn * 32 + j * 8 + 2 * c;
            float o00 = acc[i][j][0] * scale + bv0;
            float o01 = acc[i][j][1] * scale + bv0;
            float o10 = acc[i][j][2] * scale + bv1;
            float o11 = acc[i][j][3] * scale + bv1;
            if (ROUND) {
                o00 = tf32r(o00); o01 = tf32r(o01);
                o10 = tf32r(o10); o11 = tf32r(o11);
            }
            *(float2*)&C[(size_t)m * ldc + n]       = make_float2(o00, o01);
            *(float2*)&C[(size_t)(m + 8) * ldc + n] = make_float2(o10, o11);
        }
    }
}

// ---------------------------------------------------------------------------
// prep: tf32-round W and x elementwise
// ---------------------------------------------------------------------------
__global__ __launch_bounds__(256) void prep_w(
    const float* __restrict__ Wq, const float* __restrict__ Wk,
    const float* __restrict__ Wv)
{
    const int i = blockIdx.x * 256 + threadIdx.x;       // 786432
    const int p = i >> 18, rr = i & 0x3FFFF;
    g_wr[i] = tf32r((p == 0 ? Wq : p == 1 ? Wk : Wv)[rr]);
}

__global__ __launch_bounds__(256) void prep_x(const float* __restrict__ x)
{
    const size_t i = (size_t)blockIdx.x * 1024 + threadIdx.x * 4;  // vectorized
    float4 f = *(const float4*)&x[i];
    f.x = tf32r(f.x); f.y = tf32r(f.y); f.z = tf32r(f.z); f.w = tf32r(f.w);
    *(float4*)&g_xr[i] = f;
}

// ---------------------------------------------------------------------------
// GEMM kernels
// ---------------------------------------------------------------------------
__global__ __launch_bounds__(256, 2) void qkv_kernel(
    const float* __restrict__ bq, const float* __restrict__ bk,
    const float* __restrict__ bv)
{
    const int z = blockIdx.z;
    const int p = z >> 3;
    const int b = z & 7;
    const float* W  = g_wr + (size_t)p * CC * CC;
    const float* bi = (p == 0) ? bq : (p == 1) ? bk : bv;
    float* out = ((p == 0) ? g_q : (p == 1) ? g_k : g_v) + (size_t)b * CC * LL;
    const float* xb = g_xr + (size_t)b * CC * LL;
    gemm_body<false, false, true>(W, xb, out, CC, CC, LL, LL, 1.0f, bi);
}

__global__ __launch_bounds__(256, 2) void scores_kernel()
{
    const int b = blockIdx.z;
    const float* Q  = g_q + (size_t)b * CC * LL;
    const float* Kp = g_k + (size_t)b * CC * LL;
    float* S = g_s + (size_t)b * LL * LL;
    gemm_body<true, false, false>(Q, Kp, S, CC, LL, LL, LL,
                                  0.044194173824159216f, nullptr);
}

__global__ __launch_bounds__(256) void softmax_kernel()
{
    const int tid = threadIdx.x;
    float* row = g_s + (size_t)blockIdx.x * LL;

    float v[8];
    float mx = -3.402823466e38f;
#pragma unroll
    for (int i = 0; i < 8; i++) {
        v[i] = row[tid + (i << 8)];
        mx = fmaxf(mx, v[i]);
    }
    __shared__ float red[256];
    red[tid] = mx;
    __syncthreads();
    for (int s = 128; s >= 1; s >>= 1) {
        if (tid < s) red[tid] = fmaxf(red[tid], red[tid + s]);
        __syncthreads();
    }
    mx = red[0];
    __syncthreads();

    float sum = 0.0f;
#pragma unroll
    for (int i = 0; i < 8; i++) {
        v[i] = __expf(v[i] - mx);
        sum += v[i];
    }
    red[tid] = sum;
    __syncthreads();
    for (int s = 128; s >= 1; s >>= 1) {
        if (tid < s) red[tid] += red[tid + s];
        __syncthreads();
    }
    const float inv = __frcp_rn(red[0]);
#pragma unroll
    for (int i = 0; i < 8; i++)
        row[tid + (i << 8)] = tf32r(v[i] * inv);   // P pre-rounded for out GEMM
}

__global__ __launch_bounds__(256, 2) void out_kernel(float* __restrict__ out)
{
    const int b = blockIdx.z;
    const float* V = g_v + (size_t)b * CC * LL;
    const float* P = g_s + (size_t)b * LL * LL;
    float* O = out + (size_t)b * CC * LL;
    gemm_body<false, true, false>(V, P, O, LL, LL, LL, LL, 1.0f, nullptr);
}

// ---------------------------------------------------------------------------
extern "C" void kernel_launch(void* const* d_in, const int* in_sizes, int n_in,
                              void* d_out, int out_size)
{
    const float* Wq = (const float*)d_in[1];
    const float* bq = (const float*)d_in[2];
    const float* Wk = (const float*)d_in[3];
    const float* bk = (const float*)d_in[4];
    const float* Wv = (const float*)d_in[5];
    const float* bv = (const float*)d_in[6];
    const float* x  = (const float*)d_in[0];
    float* out = (float*)d_out;

    dim3 blk(256);

    prep_w<<<3 * CC * CC / 256, blk>>>(Wq, Wk, Wv);
    prep_x<<<BB * CC * LL / 1024, blk>>>(x);

    dim3 g1(LL / BN, CC / BM, 3 * BB);
    qkv_kernel<<<g1, blk>>>(bq, bk, bv);

    dim3 g2(LL / BN, LL / BM, BB);
    scores_kernel<<<g2, blk>>>();

    softmax_kernel<<<BB * LL, blk>>>();

    dim3 g4(LL / BN, CC / BM, BB);
    out_kernel<<<g4, blk>>>(out);
}

// round 12
// speedup vs baseline: 1.6445x; 1.6269x over previous
#include <cuda_runtime.h>
#include <cstdint>
#include <math.h>

#define BB 8
#define CC 512
#define LL 2048

// ---------------- global scratch (no allocation) ----------------
__device__ float g_wr[3 * CC * CC];            // tf32-rounded W (q,k,v concat)
__device__ float g_xr[BB * CC * LL];           // tf32-rounded x
__device__ float g_q[BB * CC * LL];            // tf32-rounded q  [b][c][l]
__device__ float g_k[BB * CC * LL];            // tf32-rounded k  [b][c][l]
__device__ float g_v[BB * CC * LL];            // tf32-rounded v  [b][c][l]
__device__ float g_s[(size_t)BB * LL * LL];    // scores, then tf32-rounded P

__device__ __forceinline__ float tf32r(float f) {
    unsigned u;
    asm("cvt.rna.tf32.f32 %0, %1;" : "=r"(u) : "f"(f));
    return __uint_as_float(u);
}

__device__ __forceinline__ uint32_t smem_u32(const void* p) {
    uint32_t a;
    asm("{ .reg .u64 t; cvta.to.shared.u64 t, %1; cvt.u32.u64 %0, t; }" : "=r"(a) : "l"(p));
    return a;
}

__device__ __forceinline__ void mma_tf32(float* d, const float* a, const float* b) {
    asm volatile(
        "mma.sync.aligned.m16n8k8.row.col.f32.tf32.tf32.f32 "
        "{%0,%1,%2,%3}, {%4,%5,%6,%7}, {%8,%9}, {%0,%1,%2,%3};"
        : "+f"(d[0]), "+f"(d[1]), "+f"(d[2]), "+f"(d[3])
        : "r"(__float_as_uint(a[0])), "r"(__float_as_uint(a[1])),
          "r"(__float_as_uint(a[2])), "r"(__float_as_uint(a[3])),
          "r"(__float_as_uint(b[0])), "r"(__float_as_uint(b[1])));
}

#define CP16(d, s)  asm volatile("cp.async.cg.shared.global [%0], [%1], 16;" :: "r"(d), "l"(s))
#define CPCOMMIT()  asm volatile("cp.async.commit_group;" ::: "memory")
#define CPWAIT1()   asm volatile("cp.async.wait_group 1;" ::: "memory")

// ---------------------------------------------------------------------------
// tf32 mma.sync GEMM with 3-stage cp.async pipeline, operands stored in smem
// in their NATIVE gmem orientation (no transpose-on-store).
//   ALAY: 0 = A is MxK row-major (stride-20 smem rows, conflict-free),
//         1 = A is KxM (k rows, stride-136 smem rows)
//   BLAY: 0 = B is KxN (k rows, stride-136),  1 = B is NxK (stride-20)
// C[m,n] = scale * sum_k A(m,k)*B(k,n) + bias[m]
// Block 128x128, 256 threads, 8 warps (2M x 4N), warp tile 64x32, BK=16.
// ---------------------------------------------------------------------------
constexpr int BM = 128, BN = 128, BK = 16, STAGES = 3;

template <int ALAY, int BLAY, bool ROUND>
__device__ __forceinline__ void gemm_body(
    const float* __restrict__ A, const float* __restrict__ B,
    float* __restrict__ C, int K,
    int lda, int ldb, int ldc,
    float scale, const float* __restrict__ bias)
{
    extern __shared__ float sm[];
    constexpr int AW = (ALAY == 1) ? 136 : 20;
    constexpr int AR = (ALAY == 1) ? 16 : 128;
    constexpr int BW = (BLAY == 1) ? 20 : 136;
    constexpr int BR = (BLAY == 1) ? 128 : 16;
    constexpr int ASZ = AR * AW, BSZ = BR * BW;

    float* Ab = sm;
    float* Bb = sm + STAGES * ASZ;
    const uint32_t abase = smem_u32(Ab);
    const uint32_t bbase = smem_u32(Bb);

    const int tid  = threadIdx.x;
    const int lane = tid & 31;
    const int warp = tid >> 5;
    const int wm = warp & 1;
    const int wn = warp >> 1;
    const int r = lane >> 2;
    const int c = lane & 3;
    const int m0 = blockIdx.y * BM;
    const int n0 = blockIdx.x * BN;

    float acc[4][4][4];
#pragma unroll
    for (int i = 0; i < 4; i++)
#pragma unroll
        for (int j = 0; j < 4; j++)
#pragma unroll
            for (int q = 0; q < 4; q++) acc[i][j][q] = 0.0f;

    // issue one stage's cp.async loads (A: 512 chunks, B: 512 chunks, 16B each)
    auto issue = [&](int slot, int k0) {
#pragma unroll
        for (int it = 0; it < 2; it++) {
            const int i = tid + 256 * it;
            if (ALAY == 0) {
                const int row = i >> 2, c4 = i & 3;
                CP16(abase + 4 * (slot * ASZ + row * 20 + 4 * c4),
                     A + (size_t)(m0 + row) * lda + k0 + 4 * c4);
            } else {
                const int row = i >> 5, cc = i & 31;
                CP16(abase + 4 * (slot * ASZ + row * 136 + 4 * cc),
                     A + (size_t)(k0 + row) * lda + m0 + 4 * cc);
            }
            if (BLAY == 0) {
                const int row = i >> 5, cc = i & 31;
                CP16(bbase + 4 * (slot * BSZ + row * 136 + 4 * cc),
                     B + (size_t)(k0 + row) * ldb + n0 + 4 * cc);
            } else {
                const int row = i >> 2, c4 = i & 3;
                CP16(bbase + 4 * (slot * BSZ + row * 20 + 4 * c4),
                     B + (size_t)(n0 + row) * ldb + k0 + 4 * c4);
            }
        }
    };

    auto compute = [&](int slot) {
        const float* Asl = Ab + slot * ASZ;
        const float* Bsl = Bb + slot * BSZ;
#pragma unroll
        for (int ks = 0; ks < 2; ks++) {
            const int kb = ks * 8;
            float af[4][4], bf[4][2];
#pragma unroll
            for (int i = 0; i < 4; i++) {
                const int mb = wm * 64 + i * 16;
                if (ALAY == 1) {
                    af[i][0] = Asl[(kb + c) * 136 + mb + r];
                    af[i][1] = Asl[(kb + c) * 136 + mb + r + 8];
                    af[i][2] = Asl[(kb + c + 4) * 136 + mb + r];
                    af[i][3] = Asl[(kb + c + 4) * 136 + mb + r + 8];
                } else {
                    af[i][0] = Asl[(mb + r) * 20 + kb + c];
                    af[i][1] = Asl[(mb + r + 8) * 20 + kb + c];
                    af[i][2] = Asl[(mb + r) * 20 + kb + c + 4];
                    af[i][3] = Asl[(mb + r + 8) * 20 + kb + c + 4];
                }
            }
#pragma unroll
            for (int j = 0; j < 4; j++) {
                const int nb = wn * 32 + j * 8;
                if (BLAY == 0) {
                    bf[j][0] = Bsl[(kb + c) * 136 + nb + r];
                    bf[j][1] = Bsl[(kb + c + 4) * 136 + nb + r];
                } else {
                    bf[j][0] = Bsl[(nb + r) * 20 + kb + c];
                    bf[j][1] = Bsl[(nb + r) * 20 + kb + c + 4];
                }
            }
#pragma unroll
            for (int i = 0; i < 4; i++)
#pragma unroll
                for (int j = 0; j < 4; j++)
                    mma_tf32(acc[i][j], af[i], bf[j]);
        }
    };

    // prologue: prefetch 2 stages
    issue(0, 0); CPCOMMIT();
    issue(1, BK); CPCOMMIT();

    const int NT = K / BK;
    for (int t = 0; t < NT; t++) {
        CPWAIT1();
        __syncthreads();
        compute(t % STAGES);
        const int nxt = t + STAGES - 1;
        if (nxt < NT) issue(nxt % STAGES, nxt * BK);
        CPCOMMIT();
    }

    // epilogue
#pragma unroll
    for (int i = 0; i < 4; i++) {
        const int m = m0 + wm * 64 + i * 16 + r;
        const float bv0 = bias ? __ldg(&bias[m])     : 0.0f;
        const float bv1 = bias ? __ldg(&bias[m + 8]) : 0.0f;
#pragma unroll
        for (int j = 0; j < 4; j++) {
            const int n = n0 + wn * 32 + j * 8 + 2 * c;
            float o00 = acc[i][j][0] * scale + bv0;
            float o01 = acc[i][j][1] * scale + bv0;
            float o10 = acc[i][j][2] * scale + bv1;
            float o11 = acc[i][j][3] * scale + bv1;
            if (ROUND) {
                o00 = tf32r(o00); o01 = tf32r(o01);
                o10 = tf32r(o10); o11 = tf32r(o11);
            }
            *(float2*)&C[(size_t)m * ldc + n]       = make_float2(o00, o01);
            *(float2*)&C[(size_t)(m + 8) * ldc + n] = make_float2(o10, o11);
        }
    }
}

// smem sizes (bytes) per instantiation
constexpr int SMEM_QKV = STAGES * (128 * 20 + 16 * 136) * 4;   // 56832
constexpr int SMEM_SCO = STAGES * (16 * 136 + 16 * 136) * 4;   // 52224
constexpr int SMEM_OUT = STAGES * (128 * 20 + 128 * 20) * 4;   // 61440

// ---------------------------------------------------------------------------
// prep: tf32-round W and x elementwise
// ---------------------------------------------------------------------------
__global__ __launch_bounds__(256) void prep_w(
    const float* __restrict__ Wq, const float* __restrict__ Wk,
    const float* __restrict__ Wv)
{
    const int i = blockIdx.x * 256 + threadIdx.x;       // 786432
    const int p = i >> 18, rr = i & 0x3FFFF;
    g_wr[i] = tf32r((p == 0 ? Wq : p == 1 ? Wk : Wv)[rr]);
}

__global__ __launch_bounds__(256) void prep_x(const float* __restrict__ x)
{
    const size_t i = (size_t)blockIdx.x * 1024 + threadIdx.x * 4;
    float4 f = *(const float4*)&x[i];
    f.x = tf32r(f.x); f.y = tf32r(f.y); f.z = tf32r(f.z); f.w = tf32r(f.w);
    *(float4*)&g_xr[i] = f;
}

// ---------------------------------------------------------------------------
// GEMM kernels
// ---------------------------------------------------------------------------
__global__ __launch_bounds__(256, 2) void qkv_kernel(
    const float* __restrict__ bq, const float* __restrict__ bk,
    const float* __restrict__ bv)
{
    const int z = blockIdx.z;
    const int p = z >> 3;
    const int b = z & 7;
    const float* W  = g_wr + (size_t)p * CC * CC;
    const float* bi = (p == 0) ? bq : (p == 1) ? bk : bv;
    float* out = ((p == 0) ? g_q : (p == 1) ? g_k : g_v) + (size_t)b * CC * LL;
    const float* xb = g_xr + (size_t)b * CC * LL;
    gemm_body<0, 0, true>(W, xb, out, CC, CC, LL, LL, 1.0f, bi);
}

__global__ __launch_bounds__(256, 2) void scores_kernel()
{
    const int b = blockIdx.z;
    const float* Q  = g_q + (size_t)b * CC * LL;
    const float* Kp = g_k + (size_t)b * CC * LL;
    float* S = g_s + (size_t)b * LL * LL;
    gemm_body<1, 0, false>(Q, Kp, S, CC, LL, LL, LL,
                           0.044194173824159216f, nullptr);
}

__global__ __launch_bounds__(256) void softmax_kernel()
{
    const int tid = threadIdx.x;
    float* row = g_s + (size_t)blockIdx.x * LL;

    float v[8];
    float mx = -3.402823466e38f;
#pragma unroll
    for (int i = 0; i < 8; i++) {
        v[i] = row[tid + (i << 8)];
        mx = fmaxf(mx, v[i]);
    }
    __shared__ float red[256];
    red[tid] = mx;
    __syncthreads();
    for (int s = 128; s >= 1; s >>= 1) {
        if (tid < s) red[tid] = fmaxf(red[tid], red[tid + s]);
        __syncthreads();
    }
    mx = red[0];
    __syncthreads();

    float sum = 0.0f;
#pragma unroll
    for (int i = 0; i < 8; i++) {
        v[i] = __expf(v[i] - mx);
        sum += v[i];
    }
    red[tid] = sum;
    __syncthreads();
    for (int s = 128; s >= 1; s >>= 1) {
        if (tid < s) red[tid] += red[tid + s];
        __syncthreads();
    }
    const float inv = __frcp_rn(red[0]);
#pragma unroll
    for (int i = 0; i < 8; i++)
        row[tid + (i << 8)] = tf32r(v[i] * inv);   // P pre-rounded for out GEMM
}

__global__ __launch_bounds__(256, 2) void out_kernel(float* __restrict__ out)
{
    const int b = blockIdx.z;
    const float* V = g_v + (size_t)b * CC * LL;
    const float* P = g_s + (size_t)b * LL * LL;
    float* O = out + (size_t)b * CC * LL;
    gemm_body<0, 1, false>(V, P, O, LL, LL, LL, LL, 1.0f, nullptr);
}

// ---------------------------------------------------------------------------
extern "C" void kernel_launch(void* const* d_in, const int* in_sizes, int n_in,
                              void* d_out, int out_size)
{
    const float* x  = (const float*)d_in[0];
    const float* Wq = (const float*)d_in[1];
    const float* bq = (const float*)d_in[2];
    const float* Wk = (const float*)d_in[3];
    const float* bk = (const float*)d_in[4];
    const float* Wv = (const float*)d_in[5];
    const float* bv = (const float*)d_in[6];
    float* out = (float*)d_out;

    cudaFuncSetAttribute(qkv_kernel,    cudaFuncAttributeMaxDynamicSharedMemorySize, SMEM_QKV);
    cudaFuncSetAttribute(scores_kernel, cudaFuncAttributeMaxDynamicSharedMemorySize, SMEM_SCO);
    cudaFuncSetAttribute(out_kernel,    cudaFuncAttributeMaxDynamicSharedMemorySize, SMEM_OUT);

    dim3 blk(256);

    prep_w<<<3 * CC * CC / 256, blk>>>(Wq, Wk, Wv);
    prep_x<<<BB * CC * LL / 1024, blk>>>(x);

    dim3 g1(LL / BN, CC / BM, 3 * BB);
    qkv_kernel<<<g1, blk, SMEM_QKV>>>(bq, bk, bv);

    dim3 g2(LL / BN, LL / BM, BB);
    scores_kernel<<<g2, blk, SMEM_SCO>>>();

    softmax_kernel<<<BB * LL, blk>>>();

    dim3 g4(LL / BN, CC / BM, BB);
    out_kernel<<<g4, blk, SMEM_OUT>>>(out);
}

// round 13
// speedup vs baseline: 1.7489x; 1.0635x over previous
#include <cuda_runtime.h>
#include <cstdint>
#include <math.h>

#define BB 8
#define CC 512
#define LL 2048

// ---------------- global scratch (no allocation) ----------------
__device__ float g_wr[3 * CC * CC];            // tf32-rounded W (q,k,v concat)
__device__ float g_xr[BB * CC * LL];           // tf32-rounded x
__device__ float g_q[BB * CC * LL];            // tf32-rounded q  [b][c][l]
__device__ float g_k[BB * CC * LL];            // tf32-rounded k  [b][c][l]
__device__ float g_v[BB * CC * LL];            // tf32-rounded v  [b][c][l]
__device__ float g_s[(size_t)BB * LL * LL];    // scores, then tf32-rounded P

__device__ __forceinline__ float tf32r(float f) {
    unsigned u;
    asm("cvt.rna.tf32.f32 %0, %1;" : "=r"(u) : "f"(f));
    return __uint_as_float(u);
}

__device__ __forceinline__ uint32_t smem_u32(const void* p) {
    uint32_t a;
    asm("{ .reg .u64 t; cvta.to.shared.u64 t, %1; cvt.u32.u64 %0, t; }" : "=r"(a) : "l"(p));
    return a;
}

__device__ __forceinline__ void mma_tf32(float* d, const float* a, const float* b) {
    asm volatile(
        "mma.sync.aligned.m16n8k8.row.col.f32.tf32.tf32.f32 "
        "{%0,%1,%2,%3}, {%4,%5,%6,%7}, {%8,%9}, {%0,%1,%2,%3};"
        : "+f"(d[0]), "+f"(d[1]), "+f"(d[2]), "+f"(d[3])
        : "r"(__float_as_uint(a[0])), "r"(__float_as_uint(a[1])),
          "r"(__float_as_uint(a[2])), "r"(__float_as_uint(a[3])),
          "r"(__float_as_uint(b[0])), "r"(__float_as_uint(b[1])));
}

#define CP16(d, s)  asm volatile("cp.async.cg.shared.global [%0], [%1], 16;" :: "r"(d), "l"(s))
#define CPCOMMIT()  asm volatile("cp.async.commit_group;" ::: "memory")
#define CPWAIT2()   asm volatile("cp.async.wait_group 2;" ::: "memory")

// ---------------------------------------------------------------------------
// tf32 mma.sync GEMM. 4-stage cp.async pipeline, native-orientation smem.
//   ALAY: 0 = A is MxK row-major (stride-20 rows), 1 = A is KxM (stride-136)
//   BLAY: 0 = B is KxN (stride-136),               1 = B is NxK (stride-20)
// C[m,n] = scale * sum_k A(m,k)*B(k,n) + bias[m]
// Block 128x128, 128 threads = 4 warps (2M x 2N), warp tile 64x64, BK=16.
// Per ks-step per warp: 32 LDS.32 feed 32 HMMAs (1.0 LDS/MMA).
// ---------------------------------------------------------------------------
constexpr int BM = 128, BN = 128, BK = 16, STAGES = 4;

template <int ALAY, int BLAY, bool ROUND>
__device__ __forceinline__ void gemm_body(
    const float* __restrict__ A, const float* __restrict__ B,
    float* __restrict__ C, int K,
    int lda, int ldb, int ldc,
    float scale, const float* __restrict__ bias)
{
    extern __shared__ float sm[];
    constexpr int AW = (ALAY == 1) ? 136 : 20;
    constexpr int AR = (ALAY == 1) ? 16 : 128;
    constexpr int BW = (BLAY == 1) ? 20 : 136;
    constexpr int BR = (BLAY == 1) ? 128 : 16;
    constexpr int ASZ = AR * AW, BSZ = BR * BW;

    float* Ab = sm;
    float* Bb = sm + STAGES * ASZ;
    const uint32_t abase = smem_u32(Ab);
    const uint32_t bbase = smem_u32(Bb);

    const int tid  = threadIdx.x;        // 0..127
    const int lane = tid & 31;
    const int warp = tid >> 5;           // 0..3
    const int wm = warp & 1;             // M dir (64 rows)
    const int wn = warp >> 1;            // N dir (64 cols)
    const int r = lane >> 2;             // 0..7
    const int c = lane & 3;              // 0..3
    const int m0 = blockIdx.y * BM;
    const int n0 = blockIdx.x * BN;

    float acc[4][8][4];
#pragma unroll
    for (int i = 0; i < 4; i++)
#pragma unroll
        for (int j = 0; j < 8; j++)
#pragma unroll
            for (int q = 0; q < 4; q++) acc[i][j][q] = 0.0f;

    // issue one stage (A: 512 16B-chunks, B: 512 chunks; 4 each per thread)
    auto issue = [&](int slot, int k0) {
#pragma unroll
        for (int it = 0; it < 4; it++) {
            const int i = tid + 128 * it;            // 0..511
            if (ALAY == 0) {
                const int row = i >> 2, c4 = i & 3;
                CP16(abase + 4 * (slot * ASZ + row * 20 + 4 * c4),
                     A + (size_t)(m0 + row) * lda + k0 + 4 * c4);
            } else {
                const int row = i >> 5, cc = i & 31;
                CP16(abase + 4 * (slot * ASZ + row * 136 + 4 * cc),
                     A + (size_t)(k0 + row) * lda + m0 + 4 * cc);
            }
            if (BLAY == 0) {
                const int row = i >> 5, cc = i & 31;
                CP16(bbase + 4 * (slot * BSZ + row * 136 + 4 * cc),
                     B + (size_t)(k0 + row) * ldb + n0 + 4 * cc);
            } else {
                const int row = i >> 2, c4 = i & 3;
                CP16(bbase + 4 * (slot * BSZ + row * 20 + 4 * c4),
                     B + (size_t)(n0 + row) * ldb + k0 + 4 * c4);
            }
        }
    };

    auto compute = [&](int slot) {
        const float* Asl = Ab + slot * ASZ;
        const float* Bsl = Bb + slot * BSZ;
#pragma unroll
        for (int ks = 0; ks < 2; ks++) {
            const int kb = ks * 8;
            float af[4][4], bf[8][2];
#pragma unroll
            for (int i = 0; i < 4; i++) {
                const int mb = wm * 64 + i * 16;
                if (ALAY == 1) {
                    af[i][0] = Asl[(kb + c) * 136 + mb + r];
                    af[i][1] = Asl[(kb + c) * 136 + mb + r + 8];
                    af[i][2] = Asl[(kb + c + 4) * 136 + mb + r];
                    af[i][3] = Asl[(kb + c + 4) * 136 + mb + r + 8];
                } else {
                    af[i][0] = Asl[(mb + r) * 20 + kb + c];
                    af[i][1] = Asl[(mb + r + 8) * 20 + kb + c];
                    af[i][2] = Asl[(mb + r) * 20 + kb + c + 4];
                    af[i][3] = Asl[(mb + r + 8) * 20 + kb + c + 4];
                }
            }
#pragma unroll
            for (int j = 0; j < 8; j++) {
                const int nb = wn * 64 + j * 8;
                if (BLAY == 0) {
                    bf[j][0] = Bsl[(kb + c) * 136 + nb + r];
                    bf[j][1] = Bsl[(kb + c + 4) * 136 + nb + r];
                } else {
                    bf[j][0] = Bsl[(nb + r) * 20 + kb + c];
                    bf[j][1] = Bsl[(nb + r) * 20 + kb + c + 4];
                }
            }
#pragma unroll
            for (int i = 0; i < 4; i++)
#pragma unroll
                for (int j = 0; j < 8; j++)
                    mma_tf32(acc[i][j], af[i], bf[j]);
        }
    };

    // prologue: prefetch 3 stages
    issue(0, 0);       CPCOMMIT();
    issue(1, BK);      CPCOMMIT();
    issue(2, 2 * BK);  CPCOMMIT();

    const int NT = K / BK;
    for (int t = 0; t < NT; t++) {
        CPWAIT2();                 // stage t complete (<=2 groups in flight)
        __syncthreads();
        compute(t & 3);
        const int nxt = t + 3;
        if (nxt < NT) issue(nxt & 3, nxt * BK);
        CPCOMMIT();
    }

    // epilogue
#pragma unroll
    for (int i = 0; i < 4; i++) {
        const int m = m0 + wm * 64 + i * 16 + r;
        const float bv0 = bias ? __ldg(&bias[m])     : 0.0f;
        const float bv1 = bias ? __ldg(&bias[m + 8]) : 0.0f;
#pragma unroll
        for (int j = 0; j < 8; j++) {
            const int n = n0 + wn * 64 + j * 8 + 2 * c;
            float o00 = acc[i][j][0] * scale + bv0;
            float o01 = acc[i][j][1] * scale + bv0;
            float o10 = acc[i][j][2] * scale + bv1;
            float o11 = acc[i][j][3] * scale + bv1;
            if (ROUND) {
                o00 = tf32r(o00); o01 = tf32r(o01);
                o10 = tf32r(o10); o11 = tf32r(o11);
            }
            *(float2*)&C[(size_t)m * ldc + n]       = make_float2(o00, o01);
            *(float2*)&C[(size_t)(m + 8) * ldc + n] = make_float2(o10, o11);
        }
    }
}

// smem sizes (bytes) per instantiation (4 stages)
constexpr int SMEM_QKV = STAGES * (128 * 20 + 16 * 136) * 4;   // 75776
constexpr int SMEM_SCO = STAGES * (16 * 136 + 16 * 136) * 4;   // 69632
constexpr int SMEM_OUT = STAGES * (128 * 20 + 128 * 20) * 4;   // 81920

// ---------------------------------------------------------------------------
// prep: tf32-round W and x elementwise
// ---------------------------------------------------------------------------
__global__ __launch_bounds__(256) void prep_w(
    const float* __restrict__ Wq, const float* __restrict__ Wk,
    const float* __restrict__ Wv)
{
    const int i = blockIdx.x * 256 + threadIdx.x;       // 786432
    const int p = i >> 18, rr = i & 0x3FFFF;
    g_wr[i] = tf32r((p == 0 ? Wq : p == 1 ? Wk : Wv)[rr]);
}

__global__ __launch_bounds__(256) void prep_x(const float* __restrict__ x)
{
    const size_t i = (size_t)blockIdx.x * 1024 + threadIdx.x * 4;
    float4 f = *(const float4*)&x[i];
    f.x = tf32r(f.x); f.y = tf32r(f.y); f.z = tf32r(f.z); f.w = tf32r(f.w);
    *(float4*)&g_xr[i] = f;
}

// ---------------------------------------------------------------------------
// GEMM kernels (128 threads, 2 CTAs/SM)
// ---------------------------------------------------------------------------
__global__ __launch_bounds__(128, 2) void qkv_kernel(
    const float* __restrict__ bq, const float* __restrict__ bk,
    const float* __restrict__ bv)
{
    const int z = blockIdx.z;
    const int p = z >> 3;
    const int b = z & 7;
    const float* W  = g_wr + (size_t)p * CC * CC;
    const float* bi = (p == 0) ? bq : (p == 1) ? bk : bv;
    float* out = ((p == 0) ? g_q : (p == 1) ? g_k : g_v) + (size_t)b * CC * LL;
    const float* xb = g_xr + (size_t)b * CC * LL;
    gemm_body<0, 0, true>(W, xb, out, CC, CC, LL, LL, 1.0f, bi);
}

__global__ __launch_bounds__(128, 2) void scores_kernel()
{
    const int b = blockIdx.z;
    const float* Q  = g_q + (size_t)b * CC * LL;
    const float* Kp = g_k + (size_t)b * CC * LL;
    float* S = g_s + (size_t)b * LL * LL;
    gemm_body<1, 0, false>(Q, Kp, S, CC, LL, LL, LL,
                           0.044194173824159216f, nullptr);
}

__global__ __launch_bounds__(256) void softmax_kernel()
{
    const int tid = threadIdx.x;
    float* row = g_s + (size_t)blockIdx.x * LL;

    float v[8];
    float mx = -3.402823466e38f;
#pragma unroll
    for (int i = 0; i < 8; i++) {
        v[i] = row[tid + (i << 8)];
        mx = fmaxf(mx, v[i]);
    }
    __shared__ float red[256];
    red[tid] = mx;
    __syncthreads();
    for (int s = 128; s >= 1; s >>= 1) {
        if (tid < s) red[tid] = fmaxf(red[tid], red[tid + s]);
        __syncthreads();
    }
    mx = red[0];
    __syncthreads();

    float sum = 0.0f;
#pragma unroll
    for (int i = 0; i < 8; i++) {
        v[i] = __expf(v[i] - mx);
        sum += v[i];
    }
    red[tid] = sum;
    __syncthreads();
    for (int s = 128; s >= 1; s >>= 1) {
        if (tid < s) red[tid] += red[tid + s];
        __syncthreads();
    }
    const float inv = __frcp_rn(red[0]);
#pragma unroll
    for (int i = 0; i < 8; i++)
        row[tid + (i << 8)] = tf32r(v[i] * inv);   // P pre-rounded for out GEMM
}

__global__ __launch_bounds__(128, 2) void out_kernel(float* __restrict__ out)
{
    const int b = blockIdx.z;
    const float* V = g_v + (size_t)b * CC * LL;
    const float* P = g_s + (size_t)b * LL * LL;
    float* O = out + (size_t)b * CC * LL;
    gemm_body<0, 1, false>(V, P, O, LL, LL, LL, LL, 1.0f, nullptr);
}

// ---------------------------------------------------------------------------
extern "C" void kernel_launch(void* const* d_in, const int* in_sizes, int n_in,
                              void* d_out, int out_size)
{
    const float* x  = (const float*)d_in[0];
    const float* Wq = (const float*)d_in[1];
    const float* bq = (const float*)d_in[2];
    const float* Wk = (const float*)d_in[3];
    const float* bk = (const float*)d_in[4];
    const float* Wv = (const float*)d_in[5];
    const float* bv = (const float*)d_in[6];
    float* out = (float*)d_out;

    cudaFuncSetAttribute(qkv_kernel,    cudaFuncAttributeMaxDynamicSharedMemorySize, SMEM_QKV);
    cudaFuncSetAttribute(scores_kernel, cudaFuncAttributeMaxDynamicSharedMemorySize, SMEM_SCO);
    cudaFuncSetAttribute(out_kernel,    cudaFuncAttributeMaxDynamicSharedMemorySize, SMEM_OUT);

    dim3 blk(128);

    prep_w<<<3 * CC * CC / 256, 256>>>(Wq, Wk, Wv);
    prep_x<<<BB * CC * LL / 1024, 256>>>(x);

    dim3 g1(LL / BN, CC / BM, 3 * BB);
    qkv_kernel<<<g1, blk, SMEM_QKV>>>(bq, bk, bv);

    dim3 g2(LL / BN, LL / BM, BB);
    scores_kernel<<<g2, blk, SMEM_SCO>>>();

    softmax_kernel<<<BB * LL, 256>>>();

    dim3 g4(LL / BN, CC / BM, BB);
    out_kernel<<<g4, blk, SMEM_OUT>>>(out);
}